// round 16
// baseline (speedup 1.0000x reference)
#include <cuda_runtime.h>
#include <cuda_fp16.h>
#include <cstdint>

// ============================================================================
// IterativeFixedPoint: z_{k+1} = tanh(z_k W^T + b + x), z0 = 0, 25 iterations.
// B=32768, F=256.  (sm_103 target: no tcgen05 -> legacy mma.sync)
//
// R15: HYBRID PRECISION. Contraction (L~0.55) makes early-round errors decay
// geometrically, so rounds 1..12 run in e4m3 FP8 mma.sync.m16n8k32 (2x MAC
// per instr, half the A LDS traffic) and rounds 13..24 in fp16 (restores
// accuracy: fp8 ball 1.5e-2 * L^12 << 1e-3). z1 = tanh(x+b) direct.
// FP8 B (W) frags fully register-cached (64 regs); fp16 B: 8 k-steps in regs
// + 8 from SMEM WK slice (R10 path). 2-tile interleaved pipeline as before.
// ============================================================================

static constexpr int F       = 256;
static constexpr int MB      = 32;
static constexpr int THREADS = 256;          // 8 warps
static constexpr int GRID    = 152;
static constexpr int NR8     = 12;           // fp8 MMA rounds  (r = 1..12)
static constexpr int NR16    = 12;           // fp16 MMA rounds (r = 13..24)

static constexpr int ROWB    = 528;          // fp16 row: 256 halves + 16B pad
static constexpr int ROWB8   = 272;          // fp8 row: 256 bytes + 16B pad
static constexpr int A_BYTES = MB * ROWB;    // 16896
static constexpr int A8_BYTES = MB * ROWB8;  // 8704
// SMEM map:
//  [0,135168)       W16 staging -> reused: A16_0, A16_1, C0, C1 (ends 99328)
//  [135168,204800)  W8 staging (69632) -> reused: WK16 (k-cols 128..255, 69632)
//  [204800,222208)  A8_0, A8_1
static constexpr int SMEM_A16_0 = 0;
static constexpr int SMEM_A16_1 = A_BYTES;                  // 16896
static constexpr int SMEM_C0    = 2 * A_BYTES;              // 33792
static constexpr int C_BYTES    = 32768;
static constexpr int SMEM_C1    = SMEM_C0 + C_BYTES;        // 66560
static constexpr int W_BYTES    = F * ROWB;                 // 135168
static constexpr int SMEM_WK    = W_BYTES;                  // 135168 (W8 staging, then WK16)
static constexpr int WK_ROWB    = 272;                      // 256B data + 16B pad
static constexpr int SMEM_A8_0  = SMEM_WK + 256 * WK_ROWB;  // 204800
static constexpr int SMEM_A8_1  = SMEM_A8_0 + A8_BYTES;     // 213504
static constexpr int SMEM_BYTES = SMEM_A8_1 + A8_BYTES;     // 222208

static constexpr int KS_REG = 8;             // fp16 k-steps from registers

__device__ __forceinline__ uint32_t smem_u32(const void* p) {
    uint32_t a;
    asm("{ .reg .u64 t; cvta.to.shared.u64 t, %1; cvt.u32.u64 %0, t; }"
        : "=r"(a) : "l"(p));
    return a;
}

__device__ __forceinline__ void ldsm_x4(uint32_t r[4], uint32_t addr) {
    asm volatile("ldmatrix.sync.aligned.m8n8.x4.shared.b16 {%0,%1,%2,%3}, [%4];"
                 : "=r"(r[0]), "=r"(r[1]), "=r"(r[2]), "=r"(r[3])
                 : "r"(addr));
}

__device__ __forceinline__ void mma16816(float d[4], const uint32_t a[4],
                                         uint32_t b0, uint32_t b1) {
    asm volatile(
        "mma.sync.aligned.m16n8k16.row.col.f32.f16.f16.f32 "
        "{%0,%1,%2,%3}, {%4,%5,%6,%7}, {%8,%9}, {%0,%1,%2,%3};"
        : "+f"(d[0]), "+f"(d[1]), "+f"(d[2]), "+f"(d[3])
        : "r"(a[0]), "r"(a[1]), "r"(a[2]), "r"(a[3]), "r"(b0), "r"(b1));
}

__device__ __forceinline__ void mma16832_e4m3(float d[4], const uint32_t a[4],
                                              uint32_t b0, uint32_t b1) {
    asm volatile(
        "mma.sync.aligned.m16n8k32.row.col.f32.e4m3.e4m3.f32 "
        "{%0,%1,%2,%3}, {%4,%5,%6,%7}, {%8,%9}, {%0,%1,%2,%3};"
        : "+f"(d[0]), "+f"(d[1]), "+f"(d[2]), "+f"(d[3])
        : "r"(a[0]), "r"(a[1]), "r"(a[2]), "r"(a[3]), "r"(b0), "r"(b1));
}

__device__ __forceinline__ float tanhap(float s) {
    float r;
    asm("tanh.approx.f32 %0, %1;" : "=f"(r) : "f"(s));
    return r;
}

// pack two f32 -> e4m3x2 (b16). d.lo = cvt(lo), d.hi = cvt(hi).
__device__ __forceinline__ uint16_t pack_e4m3(float hi, float lo) {
    uint16_t v;
    asm("cvt.rn.satfinite.e4m3x2.f32 %0, %1, %2;" : "=h"(v) : "f"(hi), "f"(lo));
    return v;
}

// ---------------------------------------------------------------------------
// epilogue chunk: pair p (0..15) of this thread's 32 outputs.
// FMT: 0 = fp16 SMEM, 1 = fp8 SMEM, 2 = fp32 global
template <int FMT>
__device__ __forceinline__ void epi_pair(int p, const float accE[2][4][4],
                                         char* smem, uint32_t Cepi, uint32_t Aepi,
                                         float* outRow,
                                         int qr, int qc, int nb, int tid) {
    const int im = p >> 3, jn = (p >> 1) & 3, qh = p & 1;
    const int m  = 16 * im + qr + 8 * qh;
    const int n0 = nb + 8 * jn + qc;
    const float2 cp = *reinterpret_cast<const float2*>(
        smem + Cepi + ((p * THREADS + tid) << 3));
    const float t0 = tanhap(accE[im][jn][2 * qh + 0] + cp.x);
    const float t1 = tanhap(accE[im][jn][2 * qh + 1] + cp.y);
    if (FMT == 2) {
        *reinterpret_cast<float2*>(outRow + m * F + n0) = make_float2(t0, t1);
    } else if (FMT == 1) {
        *reinterpret_cast<uint16_t*>(smem + Aepi + m * ROWB8 + n0) = pack_e4m3(t1, t0);
    } else {
        *reinterpret_cast<__half2*>(smem + Aepi + m * ROWB + n0 * 2) =
            __floats2half2_rn(t0, t1);
    }
}

template <int FMT>
__device__ __forceinline__ void epi_full(const float acc[2][4][4], char* smem,
                                         uint32_t Cbuf, uint32_t Abuf, float* outRow,
                                         int qr, int qc, int nb, int tid) {
    #pragma unroll
    for (int p = 0; p < 16; p++)
        epi_pair<FMT>(p, acc, smem, Cbuf, Abuf, outRow, qr, qc, nb, tid);
}

__device__ __forceinline__ void zero_acc(float acc[2][4][4]) {
    #pragma unroll
    for (int im = 0; im < 2; im++)
        #pragma unroll
        for (int jn = 0; jn < 4; jn++)
            #pragma unroll
            for (int q = 0; q < 4; q++)
                acc[im][jn][q] = 0.0f;
}

// ---------------------------------------------------------------------------
// FP8 window: 8 k32-steps, B fully register-cached, 2 epi pairs per k-step.
template <bool DO_EPI, int EPI_FMT>
__device__ __forceinline__ void window8(
    char* smem, uint32_t sb, uint32_t Amma8,
    float accM[2][4][4], const float accE[2][4][4],
    uint32_t Aepi, uint32_t Cepi, float* outRow,
    const uint32_t (&B8)[8][8],
    int a_rowoff8, int qr, int qc, int nb, int tid) {
    zero_acc(accM);
    const uint32_t abase = sb + Amma8 + a_rowoff8;
    uint32_t afr[2][2][4];
    ldsm_x4(afr[0][0], abase);
    ldsm_x4(afr[0][1], abase + 16 * ROWB8);
    #pragma unroll
    for (int ks = 0; ks < 8; ks++) {
        const int cur = ks & 1, nxt = cur ^ 1;
        if (ks < 7) {
            ldsm_x4(afr[nxt][0], abase + (ks + 1) * 32);
            ldsm_x4(afr[nxt][1], abase + (ks + 1) * 32 + 16 * ROWB8);
        }
        #pragma unroll
        for (int jn = 0; jn < 4; jn++) {
            const uint32_t b0 = B8[ks][(jn >> 1) * 4 + (jn & 1) * 2 + 0];
            const uint32_t b1 = B8[ks][(jn >> 1) * 4 + (jn & 1) * 2 + 1];
            mma16832_e4m3(accM[0][jn], afr[cur][0], b0, b1);
            mma16832_e4m3(accM[1][jn], afr[cur][1], b0, b1);
        }
        if (DO_EPI) {
            epi_pair<EPI_FMT>(2 * ks + 0, accE, smem, Cepi, Aepi, outRow, qr, qc, nb, tid);
            epi_pair<EPI_FMT>(2 * ks + 1, accE, smem, Cepi, Aepi, outRow, qr, qc, nb, tid);
        }
    }
}

// ---------------------------------------------------------------------------
// FP16 window (R10 structure): 16 k16-steps, B = 8 reg ks + 8 WK SMEM ks.
template <bool DO_EPI, int EPI_FMT>
__device__ __forceinline__ void window16(
    char* smem, uint32_t sb, uint32_t Amma,
    float accM[2][4][4], const float accE[2][4][4],
    uint32_t Aepi, uint32_t Cepi, float* outRow,
    const uint32_t (&Bc)[KS_REG][8], uint32_t wk0, uint32_t wk1,
    int a_rowoff, int qr, int qc, int nb, int tid) {
    zero_acc(accM);
    const uint32_t abase = sb + Amma + a_rowoff;
    uint32_t afr[2][2][4];
    uint32_t wkf[2][8];
    ldsm_x4(afr[0][0], abase);
    ldsm_x4(afr[0][1], abase + 16 * ROWB);
    #pragma unroll
    for (int ks = 0; ks < 16; ks++) {
        const int cur = ks & 1, nxt = cur ^ 1;
        if (ks < 15) {
            ldsm_x4(afr[nxt][0], abase + (ks + 1) * 32);
            ldsm_x4(afr[nxt][1], abase + (ks + 1) * 32 + 16 * ROWB);
        }
        if (ks == 6) {
            ldsm_x4(wkf[0] + 0, wk0);
            ldsm_x4(wkf[0] + 4, wk1);
        } else if (ks >= 7 && ks < 15) {
            const int t = ks + 1 - KS_REG;
            ldsm_x4(wkf[(ks + 1) & 1] + 0, wk0 + t * 32);
            ldsm_x4(wkf[(ks + 1) & 1] + 4, wk1 + t * 32);
        }
        const uint32_t* bf = (ks < KS_REG) ? Bc[ks] : wkf[ks & 1];
        #pragma unroll
        for (int jn = 0; jn < 4; jn++) {
            const uint32_t b0 = bf[(jn >> 1) * 4 + (jn & 1) * 2 + 0];
            const uint32_t b1 = bf[(jn >> 1) * 4 + (jn & 1) * 2 + 1];
            mma16816(accM[0][jn], afr[cur][0], b0, b1);
            mma16816(accM[1][jn], afr[cur][1], b0, b1);
        }
        if (DO_EPI)
            epi_pair<EPI_FMT>(ks, accE, smem, Cepi, Aepi, outRow, qr, qc, nb, tid);
    }
}

// tile prologue: c = x + b -> C (fp32 SoA); z1 = tanh(c) -> fp8 A buffer
__device__ __forceinline__ void tile_prologue8(char* smem, uint32_t A8buf, uint32_t Cbuf,
                                               const float* xRow, const float* b,
                                               int qr, int qc, int nb, int tid) {
    #pragma unroll
    for (int p = 0; p < 16; p++) {
        const int im = p >> 3, jn = (p >> 1) & 3, qh = p & 1;
        const int m  = 16 * im + qr + 8 * qh;
        const int n0 = nb + 8 * jn + qc;
        const float2 xv = *reinterpret_cast<const float2*>(xRow + m * F + n0);
        const float c0 = xv.x + __ldg(b + n0);
        const float c1 = xv.y + __ldg(b + n0 + 1);
        *reinterpret_cast<float2*>(smem + Cbuf + ((p * THREADS + tid) << 3)) =
            make_float2(c0, c1);
        *reinterpret_cast<uint16_t*>(smem + A8buf + m * ROWB8 + n0) =
            pack_e4m3(tanhap(c1), tanhap(c0));
    }
}

__global__ void __launch_bounds__(THREADS, 1)
fixed_point_kernel(const float* __restrict__ x, const float* __restrict__ W,
                   const float* __restrict__ b, float* __restrict__ out) {
    extern __shared__ char smem[];
    const uint32_t sb = smem_u32(smem);
    const int tid = threadIdx.x;
    const int wid = tid >> 5;
    const int lt  = tid & 31;
    const int nb  = wid << 5;

    // ---- 1) W -> SMEM fp16 staging ----
    for (int i = tid; i < F * F / 4; i += THREADS) {
        const int n  = i >> 6;
        const int k4 = (i & 63) << 2;
        const float4 wv = *reinterpret_cast<const float4*>(W + n * F + k4);
        __half2* dst = reinterpret_cast<__half2*>(smem + n * ROWB + k4 * 2);
        dst[0] = __floats2half2_rn(wv.x, wv.y);
        dst[1] = __floats2half2_rn(wv.z, wv.w);
    }
    __syncthreads();

    const int b_nrow = ((lt >> 4) << 3) + (lt & 7);
    const int b_koff = ((lt >> 3) & 1) << 3;   // fp16: in halves

    // ---- 2) fp16 B frags, k-steps 0..7, into registers ----
    uint32_t Bc[KS_REG][8];
    #pragma unroll
    for (int ks = 0; ks < KS_REG; ks++) {
        #pragma unroll
        for (int jh = 0; jh < 2; jh++) {
            uint32_t r[4];
            ldsm_x4(r, sb + (nb + 16 * jh + b_nrow) * ROWB + (ks * 16 + b_koff) * 2);
            Bc[ks][jh * 4 + 0] = r[0]; Bc[ks][jh * 4 + 1] = r[1];
            Bc[ks][jh * 4 + 2] = r[2]; Bc[ks][jh * 4 + 3] = r[3];
        }
    }

    // ---- 3) convert W -> e4m3 staging at [SMEM_WK, +69632) ----
    {
        const int n = tid;   // one row per thread
        #pragma unroll 4
        for (int j = 0; j < 128; j++) {
            const __half2 h = *reinterpret_cast<const __half2*>(smem + n * ROWB + 4 * j);
            const float2 f = __half22float2(h);
            *reinterpret_cast<uint16_t*>(smem + SMEM_WK + n * ROWB8 + 2 * j) =
                pack_e4m3(f.y, f.x);
        }
    }
    __syncthreads();

    // ---- 4) fp8 B frags (all 8 k32-steps) into registers ----
    uint32_t B8[8][8];
    #pragma unroll
    for (int ks = 0; ks < 8; ks++) {
        #pragma unroll
        for (int jh = 0; jh < 2; jh++) {
            uint32_t r[4];
            // u16-view: row n stride ROWB8; k32-step = 32B; lane koff in 16B units
            ldsm_x4(r, sb + SMEM_WK + (nb + 16 * jh + b_nrow) * ROWB8
                       + ks * 32 + b_koff * 2);
            B8[ks][jh * 4 + 0] = r[0]; B8[ks][jh * 4 + 1] = r[1];
            B8[ks][jh * 4 + 2] = r[2]; B8[ks][jh * 4 + 3] = r[3];
        }
    }
    __syncthreads();   // fp8 frags read -> W8 staging area reusable

    // ---- 5) repack fp16 k-cols 128..255 into WK (overwrites W8 staging) ----
    {
        const int n = tid;
        const uint4* src = reinterpret_cast<const uint4*>(smem + n * ROWB + 256);
        uint4* dst = reinterpret_cast<uint4*>(smem + SMEM_WK + n * WK_ROWB);
        #pragma unroll
        for (int q = 0; q < 16; q++) dst[q] = src[q];
    }
    __syncthreads();   // W16 staging region now reusable for A16 / C

    const int qr = lt >> 2, qc = (lt & 3) << 1;
    const int a_rowoff   = (lt & 15) * ROWB  + ((lt >> 4) << 3) * 2;
    const int a_rowoff8  = (lt & 15) * ROWB8 + ((lt >> 4) << 4);
    const uint32_t wk0 = sb + SMEM_WK + (nb + b_nrow) * WK_ROWB + b_koff * 2;
    const uint32_t wk1 = sb + SMEM_WK + (nb + 16 + b_nrow) * WK_ROWB + b_koff * 2;

    // ---- schedule: CTAs 0..111 -> 7 tiles, 112..151 -> 6 ----
    int start, cnt;
    if (blockIdx.x < 112) { cnt = 7; start = blockIdx.x * 7; }
    else                  { cnt = 6; start = 784 + (blockIdx.x - 112) * 6; }

    float acc0[2][4][4], acc1[2][4][4];

    int i = 0;
    for (; i + 1 < cnt; i += 2) {
        const float* x0 = x + (long)(start + i)     * MB * F;
        const float* x1 = x + (long)(start + i + 1) * MB * F;
        float* o0 = out + (long)(start + i)     * MB * F;
        float* o1 = out + (long)(start + i + 1) * MB * F;

        tile_prologue8(smem, SMEM_A8_0, SMEM_C0, x0, b, qr, qc, nb, tid);
        tile_prologue8(smem, SMEM_A8_1, SMEM_C1, x1, b, qr, qc, nb, tid);
        __syncthreads();

        // fill: MMA8 T0(1)
        window8<false, 1>(smem, sb, SMEM_A8_0, acc0, acc1, 0, 0, nullptr,
                          B8, a_rowoff8, qr, qc, nb, tid);
        __syncthreads();
        // r=1: MMA8 T1(1) + EPI T0(1) fp8 -> A8_0
        window8<true, 1>(smem, sb, SMEM_A8_1, acc1, acc0, SMEM_A8_0, SMEM_C0,
                         nullptr, B8, a_rowoff8, qr, qc, nb, tid);
        __syncthreads();

        #pragma unroll 1
        for (int r = 2; r <= NR8; r++) {
            // W_a: MMA8 T0(r) + EPI T1(r-1) fp8 -> A8_1
            window8<true, 1>(smem, sb, SMEM_A8_0, acc0, acc1, SMEM_A8_1, SMEM_C1,
                             nullptr, B8, a_rowoff8, qr, qc, nb, tid);
            __syncthreads();
            // W_b: MMA8 T1(r) + EPI T0(r): fp8 except r==NR8 -> fp16 A16_0
            if (r < NR8) {
                window8<true, 1>(smem, sb, SMEM_A8_1, acc1, acc0, SMEM_A8_0, SMEM_C0,
                                 nullptr, B8, a_rowoff8, qr, qc, nb, tid);
            } else {
                window8<true, 0>(smem, sb, SMEM_A8_1, acc1, acc0, SMEM_A16_0, SMEM_C0,
                                 nullptr, B8, a_rowoff8, qr, qc, nb, tid);
            }
            __syncthreads();
        }

        #pragma unroll 1
        for (int r = NR8 + 1; r <= NR8 + NR16; r++) {
            // W_a: MMA16 T0(r) + EPI T1(r-1) fp16 -> A16_1
            window16<true, 0>(smem, sb, SMEM_A16_0, acc0, acc1, SMEM_A16_1, SMEM_C1,
                              nullptr, Bc, wk0, wk1, a_rowoff, qr, qc, nb, tid);
            __syncthreads();
            // W_b: MMA16 T1(r) + EPI T0(r): fp16 except last -> global o0
            if (r < NR8 + NR16) {
                window16<true, 0>(smem, sb, SMEM_A16_1, acc1, acc0, SMEM_A16_0, SMEM_C0,
                                  nullptr, Bc, wk0, wk1, a_rowoff, qr, qc, nb, tid);
                __syncthreads();
            } else {
                window16<true, 2>(smem, sb, SMEM_A16_1, acc1, acc0, 0, SMEM_C0,
                                  o0, Bc, wk0, wk1, a_rowoff, qr, qc, nb, tid);
            }
        }
        // tail: EPI T1(last) -> global o1 (acc1 in regs)
        epi_full<2>(acc1, smem, SMEM_C1, 0, o1, qr, qc, nb, tid);
        __syncthreads();   // before next pair reuses buffers
    }

    if (i < cnt) {   // leftover single tile: serial hybrid
        const float* x0 = x + (long)(start + i) * MB * F;
        float* o0 = out + (long)(start + i) * MB * F;
        tile_prologue8(smem, SMEM_A8_0, SMEM_C0, x0, b, qr, qc, nb, tid);
        __syncthreads();
        #pragma unroll 1
        for (int r = 1; r <= NR8; r++) {
            const uint32_t Ard = (r & 1) ? SMEM_A8_0 : SMEM_A8_1;
            const uint32_t Awr8 = (r & 1) ? SMEM_A8_1 : SMEM_A8_0;
            window8<false, 1>(smem, sb, Ard, acc0, acc0, 0, SMEM_C0, nullptr,
                              B8, a_rowoff8, qr, qc, nb, tid);
            if (r < NR8)
                epi_full<1>(acc0, smem, SMEM_C0, Awr8, nullptr, qr, qc, nb, tid);
            else
                epi_full<0>(acc0, smem, SMEM_C0, SMEM_A16_0, nullptr, qr, qc, nb, tid);
            __syncthreads();
        }
        #pragma unroll 1
        for (int r = NR8 + 1; r <= NR8 + NR16; r++) {
            const uint32_t Ard = (r & 1) ? SMEM_A16_0 : SMEM_A16_1;
            const uint32_t Awr = (r & 1) ? SMEM_A16_1 : SMEM_A16_0;
            window16<false, 0>(smem, sb, Ard, acc0, acc0, 0, SMEM_C0, nullptr,
                               Bc, wk0, wk1, a_rowoff, qr, qc, nb, tid);
            if (r < NR8 + NR16)
                epi_full<0>(acc0, smem, SMEM_C0, Awr, nullptr, qr, qc, nb, tid);
            else
                epi_full<2>(acc0, smem, SMEM_C0, 0, o0, qr, qc, nb, tid);
            __syncthreads();
        }
    }
}

// ============================================================================
// Harness entry
// ============================================================================
extern "C" void kernel_launch(void* const* d_in, const int* in_sizes, int n_in,
                              void* d_out, int out_size) {
    const float* x = (const float*)d_in[0];   // [32768, 256]
    const float* W = (const float*)d_in[1];   // [256, 256]
    const float* b = (const float*)d_in[2];   // [256]
    float* out = (float*)d_out;               // [32768, 256] fp32

    cudaFuncSetAttribute(fixed_point_kernel,
                         cudaFuncAttributeMaxDynamicSharedMemorySize, SMEM_BYTES);
    fixed_point_kernel<<<GRID, THREADS, SMEM_BYTES>>>(x, W, b, out);
}